// round 12
// baseline (speedup 1.0000x reference)
#include <cuda_runtime.h>
#include <math.h>
#include <cstdint>

// ---------------- problem constants ----------------
#define Bn   256
#define Tn   512
#define INn  32
#define Hn   128
#define Sn   4
#define HQn  32
#define BTn  (Bn*Tn)          // 131072 positions
#define DTC  0.1f
#define LOG2E 1.4426950408889634f

typedef unsigned long long u64;
typedef unsigned int u32;
typedef ulonglong2 u64x2;

// ---------------- scratch (static device globals; no allocation) ----------------
__device__ float g_xp  [(size_t)BTn*Hn];        //  64 MB
__device__ float g_inp [(size_t)Sn*BTn*Hn];     // 268 MB (pair-interleaved channels)
__device__ float g_itau[(size_t)Sn*BTn*Hn];     // 268 MB (pair-interleaved channels)
__device__ float g_hT  [Sn*Bn*Hn];

// ---------------- packed fp32x2 helpers (Blackwell FFMA2) ----------------
__device__ __forceinline__ void ffma2(u64 &d, u64 a, u64 b) {
    asm("fma.rn.f32x2 %0, %1, %2, %0;" : "+l"(d) : "l"(a), "l"(b));
}
__device__ __forceinline__ void add2(u64 &d, u64 a) {
    asm("add.rn.f32x2 %0, %0, %1;" : "+l"(d) : "l"(a));
}
__device__ __forceinline__ float hsum1(u64 a0) {
    float x0, y0;
    asm("mov.b64 {%0,%1}, %2;" : "=f"(x0), "=f"(y0) : "l"(a0));
    return x0 + y0;
}
__device__ __forceinline__ float hsum2p(u64 a0, u64 a1) {
    add2(a0, a1);
    return hsum1(a0);
}
__device__ __forceinline__ float hsum4(u64 a0, u64 a1, u64 a2, u64 a3) {
    add2(a0, a1); add2(a2, a3); add2(a0, a2);
    return hsum1(a0);
}

// ---------------- fast approx math ----------------
__device__ __forceinline__ float fast_ex2(float x) {
    float r; asm("ex2.approx.f32 %0, %1;" : "=f"(r) : "f"(x)); return r;
}
__device__ __forceinline__ float fast_rcp(float x) {
    float r; asm("rcp.approx.f32 %0, %1;" : "=f"(r) : "f"(x)); return r;
}
__device__ __forceinline__ float fast_sqrt(float x) {
    float r; asm("sqrt.approx.f32 %0, %1;" : "=f"(r) : "f"(x)); return r;
}
// single-op MUFU tanh (sm_75+): ~16cy, abs err ~6e-4
__device__ __forceinline__ float tanh_mufu(float x) {
    float r; asm("tanh.approx.f32 %0, %1;" : "=f"(r) : "f"(x)); return r;
}
__device__ __forceinline__ float fast_sigmoid(float z) {
    float zc = fminf(fmaxf(z, -30.f), 30.f);
    return fast_rcp(1.f + fast_ex2(-zc * LOG2E));
}

// ---------------- cp.async helpers (8B, ca) ----------------
__device__ __forceinline__ void cp_async8(u32 dst_smem, const void* src) {
    asm volatile("cp.async.ca.shared.global [%0], [%1], 8;" :: "r"(dst_smem), "l"(src));
}
__device__ __forceinline__ void cp_commit() {
    asm volatile("cp.async.commit_group;");
}
__device__ __forceinline__ void cp_wait0() {
    asm volatile("cp.async.wait_group 0;" ::: "memory");
}

// ============================================================================
// K1: x_proj[pos, i] = x[pos, :32] @ Wp[i, :32] + bp[i]
// ============================================================================
__global__ void __launch_bounds__(128) k_xp(const float* __restrict__ x,
                                            const float* __restrict__ Wp,
                                            const float* __restrict__ bp) {
    const int i  = threadIdx.x;
    const int p0 = blockIdx.x * 32;
    __shared__ __align__(16) float xs[32][INn];

    const float4* src = (const float4*)(x + (size_t)p0 * INn);
    float4* dst = (float4*)&xs[0][0];
    dst[i]       = src[i];
    dst[i + 128] = src[i + 128];

    u64 w[16];
    {
        const u64x2* wq = (const u64x2*)(Wp + (size_t)i * INn);
#pragma unroll
        for (int m = 0; m < 8; m++) { u64x2 v = wq[m]; w[2*m] = v.x; w[2*m+1] = v.y; }
    }
    const float bias = bp[i];
    __syncthreads();

#pragma unroll 4
    for (int p = 0; p < 32; p++) {
        const u64x2* xq = (const u64x2*)&xs[p][0];
        u64 a0 = 0ull, a1 = 0ull, a2 = 0ull, a3 = 0ull;
#pragma unroll
        for (int m = 0; m < 8; m += 2) {
            u64x2 p0v = xq[m], p1v = xq[m+1];
            ffma2(a0, w[2*m],   p0v.x); ffma2(a1, w[2*m+1], p0v.y);
            ffma2(a2, w[2*m+2], p1v.x); ffma2(a3, w[2*m+3], p1v.y);
        }
        g_xp[(size_t)(p0 + p) * Hn + i] = hsum4(a0, a1, a2, a3) + bias;
    }
}

// ============================================================================
// K2: inp drive, split-K dual-channel (measured best, R9).
// ============================================================================
__global__ void __launch_bounds__(128) k_inp(const float* __restrict__ Win_w,
                                             const float* __restrict__ Win_b,
                                             const float* __restrict__ cbias) {
    const int i    = threadIdx.x;
    const int s    = blockIdx.y;
    const int p0   = blockIdx.x * 64;
    const int wd   = i >> 5;
    const int lane = i & 31;
    const int half = lane >> 4;
    const int c    = wd * 16 + (lane & 15);   // 0..63
    __shared__ __align__(16) float xs[64][Hn];   // 32 KB

    const float4* src = (const float4*)(g_xp + (size_t)p0 * Hn);
    float4* dst = (float4*)&xs[0][0];
#pragma unroll
    for (int r = i; r < 2048; r += 128) dst[r] = src[r];

    u64 wA[32], wB[32];
    {
        const u64x2* wqA = (const u64x2*)(Win_w + ((size_t)s * Hn + c) * Hn + half * 64);
        const u64x2* wqB = (const u64x2*)(Win_w + ((size_t)s * Hn + c + 64) * Hn + half * 64);
#pragma unroll
        for (int m = 0; m < 16; m++) { u64x2 v = wqA[m]; wA[2*m] = v.x; wA[2*m+1] = v.y; }
#pragma unroll
        for (int m = 0; m < 16; m++) { u64x2 v = wqB[m]; wB[2*m] = v.x; wB[2*m+1] = v.y; }
    }
    const float biasA = Win_b[s * Hn + c]      + cbias[s * Hn + c];
    const float biasB = Win_b[s * Hn + c + 64] + cbias[s * Hn + c + 64];
    __syncthreads();

    float* outp = g_inp + ((size_t)s * BTn + p0) * Hn + 2 * c;
#pragma unroll 2
    for (int p = 0; p < 64; p++) {
        const u64x2* xq = (const u64x2*)(&xs[p][half * 64]);
        u64 a0 = 0ull, a1 = 0ull, b0 = 0ull, b1 = 0ull;
#pragma unroll
        for (int m = 0; m < 16; m++) {
            const u64x2 hv = xq[m];
            ffma2(a0, wA[2*m],   hv.x); ffma2(b0, wB[2*m],   hv.x);
            ffma2(a1, wA[2*m+1], hv.y); ffma2(b1, wB[2*m+1], hv.y);
        }
        float pA = hsum2p(a0, a1);
        float pB = hsum2p(b0, b1);
        pA += __shfl_xor_sync(0xffffffffu, pA, 16);
        pB += __shfl_xor_sync(0xffffffffu, pB, 16);
        if (half == 0) {
            float2 v = make_float2(pA + biasA, pB + biasB);
            __stwt((float2*)(outp + (size_t)p * Hn), v);
        }
    }
}

// ============================================================================
// K3: volatility gate -> itau (R9 structure).
// ============================================================================
__global__ void __launch_bounds__(128) k_itau(const float* __restrict__ v1w,
                                              const float* __restrict__ v1b,
                                              const float* __restrict__ v2w,
                                              const float* __restrict__ v2b,
                                              const float* __restrict__ tau_base) {
    const int i    = threadIdx.x;
    const int s    = blockIdx.y;
    const int p0   = blockIdx.x * 64;
    const int wd   = i >> 5;
    const int lane = i & 31;
    __shared__ __align__(16) float xs[64][Hn];   // 32 KB
    __shared__ __align__(16) float gs[64][HQn];  //  8 KB

    const float4* src = (const float4*)(g_xp + (size_t)p0 * Hn);
    float4* dst = (float4*)&xs[0][0];
#pragma unroll
    for (int r = i; r < 2048; r += 128) dst[r] = src[r];
    __syncthreads();

    // ---- stage 1: g = relu(xp @ v1w.T + v1b), split-K dual-output ----
    {
        const int half = lane >> 4;
        const int q    = lane & 15;
        u64 wA[32], wB[32];
        const u64x2* wqA = (const u64x2*)(v1w + ((size_t)s * HQn + q) * Hn + half * 64);
        const u64x2* wqB = (const u64x2*)(v1w + ((size_t)s * HQn + q + 16) * Hn + half * 64);
#pragma unroll
        for (int m = 0; m < 16; m++) { u64x2 v = wqA[m]; wA[2*m] = v.x; wA[2*m+1] = v.y; }
#pragma unroll
        for (int m = 0; m < 16; m++) { u64x2 v = wqB[m]; wB[2*m] = v.x; wB[2*m+1] = v.y; }
        const float b1A = v1b[s * HQn + q];
        const float b1B = v1b[s * HQn + q + 16];
#pragma unroll 2
        for (int pp = 0; pp < 16; pp++) {
            const int p = wd * 16 + pp;
            const u64x2* xq = (const u64x2*)(&xs[p][half * 64]);
            u64 a0 = 0ull, a1 = 0ull, b0 = 0ull, b1 = 0ull;
#pragma unroll
            for (int m = 0; m < 16; m++) {
                const u64x2 hv = xq[m];
                ffma2(a0, wA[2*m],   hv.x); ffma2(b0, wB[2*m],   hv.x);
                ffma2(a1, wA[2*m+1], hv.y); ffma2(b1, wB[2*m+1], hv.y);
            }
            float pA = hsum2p(a0, a1);
            float pB = hsum2p(b0, b1);
            pA += __shfl_xor_sync(0xffffffffu, pA, 16);
            pB += __shfl_xor_sync(0xffffffffu, pB, 16);
            if (half == 0) {
                gs[p][q]      = fmaxf(pA + b1A, 0.f);
                gs[p][q + 16] = fmaxf(pB + b1B, 0.f);
            }
        }
    }
    __syncthreads();

    // ---- stage 2: vol -> itau (channel-permuted, coalesced store) ----
    {
        const int c = ((i & 1) << 6) | (i >> 1);
        u64 w2[16];
        const u64x2* wq = (const u64x2*)(v2w + ((size_t)s * Hn + c) * HQn);
#pragma unroll
        for (int m = 0; m < 8; m++) { u64x2 v = wq[m]; w2[2*m] = v.x; w2[2*m+1] = v.y; }
        const float b2 = v2b[s * Hn + c];
        const float tb = tau_base[s * Hn + c];
        float* outp = g_itau + ((size_t)s * BTn + p0) * Hn + i;
#pragma unroll 2
        for (int p = 0; p < 64; p++) {
            const u64x2* gq = (const u64x2*)&gs[p][0];
            u64 a0 = 0ull, a1 = 0ull, a2 = 0ull, a3 = 0ull;
#pragma unroll
            for (int m = 0; m < 8; m += 2) {
                u64x2 p0v = gq[m], p1v = gq[m+1];
                ffma2(a0, w2[2*m],   p0v.x); ffma2(a1, w2[2*m+1], p0v.y);
                ffma2(a2, w2[2*m+2], p1v.x); ffma2(a3, w2[2*m+3], p1v.y);
            }
            const float z   = hsum4(a0, a1, a2, a3) + b2;
            const float vol = fast_sigmoid(z);
            float tau = tb * (0.2f + 1.8f * (1.f - vol));
            tau = fminf(fmaxf(tau, 0.1f), 10.f);
            __stwt(outp + (size_t)p * Hn, 1.f / tau);
        }
    }
}

// ============================================================================
// K4: liquid-cell scan, DUAL-ROW at 3 CTAs/SM.
// One CTA = 2 batch rows of the same scale; shared Wrec registers (128).
// __launch_bounds__(128,3) pins 3 CTAs/SM (<=170 regs; cold per-timestep
// state may spill, inner loop stays in regs). Drive values for t+1 are
// prefetched into smem via cp.async (no register residency): half0 lanes
// fetch inp (rows A,B), half1 lanes fetch itau; one extra barrier per
// timestep publishes them. Inner step = R8 dual-row body + MUFU tanh:
// all per-row chains independent -> 2x ILP per warp fills the stall cycles
// the R9 profile exposed (issue 41.5%, 440cy unhidden stall per step).
// ============================================================================
__global__ void __launch_bounds__(128, 3) k_scan(const float* __restrict__ Wrec) {
    const int bid  = blockIdx.x;              // 0..511
    const int s    = 3 - (bid >> 7);          // heavy scale first (LPT)
    const int bp   = bid & 127;
    const int t    = threadIdx.x;
    const int wid  = t >> 5;
    const int lane = t & 31;
    const int half = lane >> 4;                 // K-half
    const int cc   = wid * 16 + (lane & 15);    // 0..63

    __shared__ __align__(16) float h_s[2][Hn];
    __shared__ __align__(16) float red[2][4];
    __shared__ __align__(16) float2 drv[2][4][64];  // [buf][inpA,inpB,itauA,itauB][cc]

    // two half-rows of Wrec in registers (channels cc and cc+64) — shared by both rows
    u64 w1[32], w2[32];
    {
        const u64x2* wq1 = (const u64x2*)(Wrec + ((size_t)s * Hn + cc) * Hn + half * 64);
        const u64x2* wq2 = (const u64x2*)(Wrec + ((size_t)s * Hn + cc + 64) * Hn + half * 64);
#pragma unroll
        for (int m = 0; m < 16; m++) { u64x2 v = wq1[m]; w1[2*m] = v.x; w1[2*m+1] = v.y; }
#pragma unroll
        for (int m = 0; m < 16; m++) { u64x2 v = wq2[m]; w2[2*m] = v.x; w2[2*m+1] = v.y; }
    }

    const size_t rowA = (size_t)(s * Bn + 2 * bp);
    const float2* gIA = (const float2*)g_inp  + rowA * Tn * 64 + cc;
    const float2* gTA = (const float2*)g_itau + rowA * Tn * 64 + cc;

    // smem addresses for this thread's cp.async destinations
    const u32 drv_base = (u32)__cvta_generic_to_shared(&drv[0][0][0]);
    // strides: [buf] = 4*64*8 = 2048 B; [arr] = 64*8 = 512 B; [cc] = 8 B
    const u32 my_a0 = drv_base + (half == 0 ? 0u : 2u) * 512u + (u32)cc * 8u;
    const u32 my_a1 = my_a0 + 512u;
    const float2* my_s0 = (half == 0) ? gIA : gTA;                    // row A source
    const float2* my_s1 = my_s0 + (size_t)Tn * 64;                    // row B source

    // prefetch t=0
    cp_async8(my_a0, my_s0);
    cp_async8(my_a1, my_s1);
    cp_commit();

    float hA1 = 0.f, hA2 = 0.f;
    float hB1 = 0.f, hB2 = 0.f;
    h_s[0][t] = 0.f;
    h_s[1][t] = 0.f;
    const int nsteps = 3 + 2 * s;

    cp_wait0();
    __syncthreads();

    int buf = 0;
    for (int tt = 0; tt < Tn; tt++) {
        // read current drive from smem
        const float2 inpA  = drv[buf][0][cc];
        const float2 inpB  = drv[buf][1][cc];
        const float2 itauA = drv[buf][2][cc];
        const float2 itauB = drv[buf][3][cc];

        // prefetch t+1 into the other buffer
        if (tt + 1 < Tn) {
            const u32 off = (u32)(buf ^ 1) * 2048u;
            const size_t goff = (size_t)(tt + 1) * 64;
            cp_async8(my_a0 + off, my_s0 + goff);
            cp_async8(my_a1 + off, my_s1 + goff);
            cp_commit();
        }

        for (int k = 0; k < nsteps; k++) {
            // interleaved partial dots: 2 rows x 2 output channels
            const u64x2* hqA = (const u64x2*)(h_s[0] + half * 64);
            const u64x2* hqB = (const u64x2*)(h_s[1] + half * 64);
            u64 a0 = 0ull, a1 = 0ull, b0 = 0ull, b1 = 0ull;
            u64 c0 = 0ull, c1 = 0ull, d0 = 0ull, d1 = 0ull;
#pragma unroll
            for (int m = 0; m < 16; m++) {
                const u64x2 hvA = hqA[m];
                const u64x2 hvB = hqB[m];
                ffma2(a0, w1[2*m],   hvA.x); ffma2(b0, w2[2*m],   hvA.x);
                ffma2(c0, w1[2*m],   hvB.x); ffma2(d0, w2[2*m],   hvB.x);
                ffma2(a1, w1[2*m+1], hvA.y); ffma2(b1, w2[2*m+1], hvA.y);
                ffma2(c1, w1[2*m+1], hvB.y); ffma2(d1, w2[2*m+1], hvB.y);
            }
            float pA1 = hsum2p(a0, a1);
            float pA2 = hsum2p(b0, b1);
            float pB1 = hsum2p(c0, c1);
            float pB2 = hsum2p(d0, d1);
            pA1 += __shfl_xor_sync(0xffffffffu, pA1, 16);
            pA2 += __shfl_xor_sync(0xffffffffu, pA2, 16);
            pB1 += __shfl_xor_sync(0xffffffffu, pB1, 16);
            pB2 += __shfl_xor_sync(0xffffffffu, pB2, 16);

            const float dhA1 = (tanh_mufu(pA1 + inpA.x) - hA1) * itauA.x;
            const float dhA2 = (tanh_mufu(pA2 + inpA.y) - hA2) * itauA.y;
            const float dhB1 = (tanh_mufu(pB1 + inpB.x) - hB1) * itauB.x;
            const float dhB2 = (tanh_mufu(pB2 + inpB.y) - hB2) * itauB.y;

            // norms: halves duplicate -> {1,2,4,8} per row, interleaved
            float sqA = fmaf(dhA1, dhA1, dhA2 * dhA2);
            float sqB = fmaf(dhB1, dhB1, dhB2 * dhB2);
            sqA += __shfl_xor_sync(0xffffffffu, sqA, 1);
            sqB += __shfl_xor_sync(0xffffffffu, sqB, 1);
            sqA += __shfl_xor_sync(0xffffffffu, sqA, 2);
            sqB += __shfl_xor_sync(0xffffffffu, sqB, 2);
            sqA += __shfl_xor_sync(0xffffffffu, sqA, 4);
            sqB += __shfl_xor_sync(0xffffffffu, sqB, 4);
            sqA += __shfl_xor_sync(0xffffffffu, sqA, 8);
            sqB += __shfl_xor_sync(0xffffffffu, sqB, 8);
            if (lane == 0) { red[0][wid] = sqA; red[1][wid] = sqB; }
            __syncthreads();
            const float4 rA = *(const float4*)red[0];
            const float4 rB = *(const float4*)red[1];
            const float magA = fast_sqrt((rA.x + rA.y) + (rA.z + rA.w));
            const float magB = fast_sqrt((rB.x + rB.y) + (rB.z + rB.w));
            const float scA = DTC * fast_rcp(fmaf(0.2f, magA, 1.f));
            const float scB = DTC * fast_rcp(fmaf(0.2f, magB, 1.f));
            hA1 = fmaf(scA, dhA1, hA1);  hA2 = fmaf(scA, dhA2, hA2);
            hB1 = fmaf(scB, dhB1, hB1);  hB2 = fmaf(scB, dhB2, hB2);
            if (half == 0) {
                h_s[0][cc] = hA1;  h_s[0][cc + 64] = hA2;
                h_s[1][cc] = hB1;  h_s[1][cc + 64] = hB2;
            }
            __syncthreads();
        }

        cp_wait0();          // t+1 drive landed (issued ~nsteps*step ago)
        __syncthreads();     // publish cross-half
        buf ^= 1;
    }
    if (half == 0) {
        float* oA = g_hT + rowA * Hn;
        oA[cc]           = hA1;
        oA[cc + 64]      = hA2;
        oA[Hn + cc]      = hB1;
        oA[Hn + cc + 64] = hB2;
    }
}

// ============================================================================
// K5: projection heads + fusion MLP. One CTA per batch row.
// ============================================================================
__global__ void __launch_bounds__(128) k_head(const float* __restrict__ proj_w,
                                              const float* __restrict__ proj_b,
                                              const float* __restrict__ f1_w,
                                              const float* __restrict__ f1_b,
                                              const float* __restrict__ f2_w,
                                              const float* __restrict__ f2_b,
                                              const float* __restrict__ f3_w,
                                              const float* __restrict__ f3_b,
                                              float* __restrict__ out) {
    const int b = blockIdx.x;
    const int i = threadIdx.x;
    __shared__ float fs[Hn];
    __shared__ float h1s[Hn];
    __shared__ float h2s[64];
    __shared__ float rs[4];

    {
        const int s = i >> 5, q = i & 31;
        const float* hrow = g_hT + (size_t)(s * Bn + b) * Hn;
        const float* pw   = proj_w + (size_t)(s * 32 + q) * Hn;
        float acc = proj_b[s * 32 + q];
#pragma unroll 8
        for (int j = 0; j < Hn; j++) acc += hrow[j] * pw[j];
        fs[i] = acc;
    }
    __syncthreads();

    {
        const float* w1 = f1_w + (size_t)i * Hn;
        float acc = f1_b[i];
#pragma unroll 8
        for (int j = 0; j < Hn; j++) acc += fs[j] * w1[j];
        h1s[i] = fmaxf(acc, 0.f);
    }
    __syncthreads();

    if (i < 64) {
        const float* w2 = f2_w + (size_t)i * Hn;
        float acc = f2_b[i];
#pragma unroll 8
        for (int j = 0; j < Hn; j++) acc += h1s[j] * w2[j];
        h2s[i] = fmaxf(acc, 0.f);
    }
    __syncthreads();

    float pr = (i < 64) ? h2s[i] * f3_w[i] : 0.f;
#pragma unroll
    for (int off = 16; off; off >>= 1) pr += __shfl_xor_sync(0xffffffffu, pr, off);
    if ((i & 31) == 0) rs[i >> 5] = pr;
    __syncthreads();
    if (i == 0) out[b] = rs[0] + rs[1] + f3_b[0];
}

// ============================================================================
extern "C" void kernel_launch(void* const* d_in, const int* in_sizes, int n_in,
                              void* d_out, int out_size) {
    (void)in_sizes; (void)n_in; (void)out_size;
    const float* x        = (const float*)d_in[0];
    const float* Wp       = (const float*)d_in[1];
    const float* bp       = (const float*)d_in[2];
    const float* Wrec     = (const float*)d_in[3];
    const float* Win_w    = (const float*)d_in[4];
    const float* Win_b    = (const float*)d_in[5];
    const float* cbias    = (const float*)d_in[6];
    const float* tau_base = (const float*)d_in[7];
    const float* vg1_w    = (const float*)d_in[8];
    const float* vg1_b    = (const float*)d_in[9];
    const float* vg2_w    = (const float*)d_in[10];
    const float* vg2_b    = (const float*)d_in[11];
    const float* proj_w   = (const float*)d_in[12];
    const float* proj_b   = (const float*)d_in[13];
    const float* f1_w     = (const float*)d_in[14];
    const float* f1_b     = (const float*)d_in[15];
    const float* f2_w     = (const float*)d_in[16];
    const float* f2_b     = (const float*)d_in[17];
    const float* f3_w     = (const float*)d_in[18];
    const float* f3_b     = (const float*)d_in[19];
    float* out = (float*)d_out;

    k_xp  <<<BTn / 32, 128>>>(x, Wp, bp);
    k_inp <<<dim3(BTn / 64, Sn), 128>>>(Win_w, Win_b, cbias);
    k_itau<<<dim3(BTn / 64, Sn), 128>>>(vg1_w, vg1_b, vg2_w, vg2_b, tau_base);
    k_scan<<<Sn * Bn / 2, 128>>>(Wrec);
    k_head<<<Bn, 128>>>(proj_w, proj_b, f1_w, f1_b, f2_w, f2_b, f3_w, f3_b, out);
}